// round 11
// baseline (speedup 1.0000x reference)
#include <cuda_runtime.h>
#include <cuda_bf16.h>
#include <float.h>
#include <math.h>
#include <stdint.h>

// ---------------- problem constants ----------------
constexpr int   Bn   = 16;
constexpr int   Nn   = 33600;
constexpr int   Cc   = 80;
constexpr int   MAXN = 100;
constexpr float THR  = 0.05f;
constexpr float IOUT = 0.65f;

// local-histogram constants: bucket = (bits - BASE) >> 14
constexpr unsigned BASE = 0x3D000000u;   // below bits(0.05)=0x3D4CCCCD
constexpr int      HB   = 2560;          // (0x3F800000-BASE)>>14 = 256*10
constexpr int      CAP  = 2048;          // candidate record capacity per batch
constexpr int      SLICES = 8;           // compact CTAs per batch
constexpr int      SLICE_A = Nn / SLICES;        // 4200 anchors
constexpr int      SLICE_V = SLICE_A / 2;        // 2100 uint4 (2 anchors each)

// ---------------- device scratch ----------------
__device__ uint2              g_sl[Bn * Nn];      // {score_bits (0 if <THR), label}
__device__ int                g_cnt[Bn];          // candidate counters; re-zeroed by k_nms
__device__ unsigned long long g_key[Bn * CAP];    // score_bits<<32 | ~idx
__device__ float4             g_boxr[Bn * CAP];   // decoded box
__device__ int                g_labr[Bn * CAP];   // label

// ---------------- kernel 1: sigmoid + max/argmax + packed store (no atomics) ----------------
// 4 lanes per anchor; each lane reads 20 floats (5x float4), default cache policy.
__global__ void k_score(const float* __restrict__ cls,
                        const float* __restrict__ obj) {
    int t   = blockIdx.x * blockDim.x + threadIdx.x;
    int a   = t >> 2;          // anchor
    int sub = t & 3;
    if (a >= Bn * Nn) return;

    const float4* p = reinterpret_cast<const float4*>(cls + (size_t)a * Cc + sub * 20);
    float mx = -FLT_MAX;
    int   mi = 0;
#pragma unroll
    for (int i = 0; i < 5; i++) {
        float4 v = p[i];
        int base = sub * 20 + i * 4;
        if (v.x > mx) { mx = v.x; mi = base; }
        if (v.y > mx) { mx = v.y; mi = base + 1; }
        if (v.z > mx) { mx = v.z; mi = base + 2; }
        if (v.w > mx) { mx = v.w; mi = base + 3; }
    }
#pragma unroll
    for (int off = 1; off < 4; off <<= 1) {
        float om  = __shfl_xor_sync(0xffffffffu, mx, off);
        int   omi = __shfl_xor_sync(0xffffffffu, mi, off);
        if (om > mx || (om == mx && omi < mi)) { mx = om; mi = omi; }
    }
    if (sub == 0) {
        float o = obj[a];
        float s = (1.0f / (1.0f + __expf(-mx))) * (1.0f / (1.0f + __expf(-o)));
        unsigned bits = (s >= THR) ? __float_as_uint(s) : 0u;
        g_sl[a] = make_uint2(bits, (unsigned)mi);
    }
}

// intra-warp inclusive suffix sum over 32 lanes
__device__ __forceinline__ unsigned warp_suffix_sum(unsigned v, int lane) {
#pragma unroll
    for (int o = 1; o < 32; o <<= 1) {
        unsigned u = __shfl_down_sync(0xffffffffu, v, o);
        if (lane + o < 32) v += u;
    }
    return v;
}

// ---------------- kernel 2: per-slice LOCAL histogram + threshold + compact + decode ----------------
// Exactness: global top-100 of a batch is a subset of the union of per-slice top-100s.
__global__ void __launch_bounds__(256, 4)
k_compact(const float* __restrict__ bbox,
          const float* __restrict__ priors) {
    __shared__ unsigned hist[HB];      // 10KB, slice-local
    __shared__ unsigned csum[256];
    __shared__ unsigned wsum[8];
    __shared__ unsigned sTB;

    int b    = blockIdx.x >> 3;
    int s    = blockIdx.x & 7;
    int tid  = threadIdx.x;
    int lane = tid & 31;
    int wid  = tid >> 5;

    // zero local histogram
#pragma unroll
    for (int i = 0; i < HB / 256; i++) hist[tid + i * 256] = 0u;
    __syncthreads();

    // local histogram of this slice's score bits
    const uint4* sp = reinterpret_cast<const uint4*>(g_sl + (size_t)b * Nn + s * SLICE_A);
    for (int i = tid; i < SLICE_V; i += 256) {
        uint4 v = sp[i];   // {bits0, lab0, bits1, lab1}
        if (v.x) {
            unsigned bk = (v.x - BASE) >> 14;
            if (bk >= (unsigned)HB) bk = HB - 1;
            atomicAdd(&hist[bk], 1u);
        }
        if (v.z) {
            unsigned bk = (v.z - BASE) >> 14;
            if (bk >= (unsigned)HB) bk = HB - 1;
            atomicAdd(&hist[bk], 1u);
        }
    }
    __syncthreads();

    // chunk sums: 10 buckets per thread
    unsigned cs = 0;
#pragma unroll
    for (int i = 0; i < 10; i++) cs += hist[tid * 10 + i];

    // suffix scan over 256 chunk sums
    unsigned suf = warp_suffix_sum(cs, lane);
    if (lane == 0) wsum[wid] = suf;
    __syncthreads();
    if (wid == 0 && lane < 8) {
        unsigned wv = wsum[lane];
#pragma unroll
        for (int o = 1; o < 8; o <<= 1) {
            unsigned u = __shfl_down_sync(0xffu, wv, o);
            if (lane + o < 8) wv += u;
        }
        wsum[lane] = wv;
    }
    if (tid == 0) sTB = 0u;   // doubles as boundary-chunk slot
    __syncthreads();
    unsigned suffTotal = suf + ((wid < 7) ? wsum[wid + 1] : 0u);
    csum[tid] = suffTotal;
    __syncthreads();
    if (suffTotal >= (unsigned)MAXN &&
        (tid == 255 || csum[tid + 1] < (unsigned)MAXN))
        sTB = tid;            // boundary chunk index
    __syncthreads();
    if (tid == 0) {
        int c = (int)sTB;
        int cum = (c < 255) ? (int)csum[c + 1] : 0;
        int bstart = c * 10;
        int bb = bstart + 9;
        for (; bb >= bstart; bb--) {
            cum += (int)hist[bb];
            if (cum >= MAXN) break;
        }
        int bucket = (bb < bstart) ? bstart : bb;   // slice has <100 valid -> take all
        sTB = BASE + ((unsigned)bucket << 14);
    }
    __syncthreads();
    unsigned TB = sTB;

    // compact + decode this slice's local top candidates
    for (int i = tid; i < SLICE_V; i += 256) {
        uint4 v = sp[i];
#pragma unroll
        for (int h = 0; h < 2; h++) {
            unsigned bits = h ? v.z : v.x;
            unsigned lab  = h ? v.w : v.y;
            if (bits >= TB) {
                int idx = s * SLICE_A + 2 * i + h;
                int pos = atomicAdd(&g_cnt[b], 1);
                if (pos < CAP) {
                    float4 pr = reinterpret_cast<const float4*>(priors)[idx];
                    float4 bp = reinterpret_cast<const float4*>(bbox)[(size_t)b * Nn + idx];
                    float cx = bp.x * pr.z + pr.x;
                    float cy = bp.y * pr.w + pr.y;
                    float w  = __expf(bp.z) * pr.z;
                    float hh = __expf(bp.w) * pr.w;
                    g_key[b * CAP + pos]  = ((unsigned long long)bits << 32) | (unsigned)(~idx);
                    g_boxr[b * CAP + pos] = make_float4(cx - 0.5f * w, cy - 0.5f * hh,
                                                        cx + 0.5f * w, cy + 0.5f * hh);
                    g_labr[b * CAP + pos] = (int)lab;
                }
            }
        }
    }
}

// ---------------- kernel 3: rank + matrix NMS + write + counter rezero ----------------
__global__ void __launch_bounds__(1024, 1)
k_nms(float* __restrict__ out, int write_keep) {
    __shared__ unsigned long long keys[CAP];
    __shared__ int      spos[128];
    __shared__ float4   bx4[MAXN];
    __shared__ float    ars[MAXN];
    __shared__ float    sss[MAXN];
    __shared__ int      lls[MAXN];
    __shared__ unsigned sup[MAXN][4];
    __shared__ unsigned kin[4];
    __shared__ unsigned kout[4];

    int b   = blockIdx.x;
    int tid = threadIdx.x;

    int cnt = g_cnt[b]; if (cnt > CAP) cnt = CAP;
    for (int i = tid; i < cnt; i += 1024) keys[i] = g_key[b * CAP + i];
    if (tid < 128) spos[tid] = -1;
    if (tid < 4)   kin[tid] = 0u;
    __syncthreads();

    // exact rank (keys unique: ~idx in low bits); handles cnt > blockDim
    for (int c0 = tid; c0 < cnt; c0 += 1024) {
        unsigned long long mk = keys[c0];
        int r = 0;
        for (int j = 0; j < cnt; j++) r += (keys[j] > mk);
        if (r < 128) spos[r] = c0;
    }
    __syncthreads();

    // decode winners into smem
    if (tid < MAXN) {
        sup[tid][0] = 0u; sup[tid][1] = 0u; sup[tid][2] = 0u; sup[tid][3] = 0u;
        int p = spos[tid];
        if (p >= 0) {
            float4 bb = g_boxr[b * CAP + p];   // L2-hot
            bx4[tid] = bb;
            ars[tid] = (bb.z - bb.x) * (bb.w - bb.y);
            sss[tid] = __uint_as_float((unsigned)(keys[p] >> 32));
            lls[tid] = g_labr[b * CAP + p];
            atomicOr(&kin[tid >> 5], 1u << (tid & 31));
        } else {
            bx4[tid] = make_float4(0.f, 0.f, 0.f, 0.f);
            ars[tid] = 0.f; sss[tid] = 0.f; lls[tid] = -1;
        }
    }
    __syncthreads();

    // parallel pairwise suppression matrix (r > i, same label, IoU >= thr)
    for (int p = tid; p < MAXN * MAXN; p += 1024) {
        int i = p / MAXN;
        int r = p - i * MAXN;
        if (r > i) {
            int li = lls[i];
            if (li >= 0 && li == lls[r]) {
                float4 bi = bx4[i];
                float4 br = bx4[r];
                float ix1 = fmaxf(br.x, bi.x);
                float iy1 = fmaxf(br.y, bi.y);
                float ix2 = fminf(br.z, bi.z);
                float iy2 = fminf(br.w, bi.w);
                float inter = fmaxf(ix2 - ix1, 0.0f) * fmaxf(iy2 - iy1, 0.0f);
                float uni   = ars[i] + ars[r] - inter;
                if (inter / (uni + 1e-8f) >= IOUT)
                    atomicOr(&sup[i][r >> 5], 1u << (r & 31));
            }
        }
    }
    __syncthreads();

    // greedy scan: software-pipelined register bit logic on one thread
    if (tid == 0) {
        unsigned k0 = kin[0], k1 = kin[1], k2 = kin[2], k3 = kin[3];
        unsigned n0 = sup[0][0], n1 = sup[0][1], n2 = sup[0][2], n3 = sup[0][3];
        for (int i = 0; i < MAXN - 1; i++) {
            unsigned c0 = n0, c1 = n1, c2 = n2, c3 = n3;
            n0 = sup[i + 1][0]; n1 = sup[i + 1][1];
            n2 = sup[i + 1][2]; n3 = sup[i + 1][3];
            unsigned kw = (i < 32) ? k0 : (i < 64) ? k1 : (i < 96) ? k2 : k3;
            if ((kw >> (i & 31)) & 1u) {
                k0 &= ~c0; k1 &= ~c1; k2 &= ~c2; k3 &= ~c3;
            }
        }
        kout[0] = k0; kout[1] = k1; kout[2] = k2; kout[3] = k3;
    }
    __syncthreads();

    // write output
    if (tid < MAXN) {
        bool kept = (kout[tid >> 5] >> (tid & 31)) & 1u;
        float* row = out + ((size_t)b * MAXN + tid) * 6;
        if (kept) {
            float4 bb = bx4[tid];
            row[0] = bb.x; row[1] = bb.y; row[2] = bb.z; row[3] = bb.w;
            row[4] = sss[tid]; row[5] = (float)lls[tid];
        } else {
            row[0] = 0.0f; row[1] = 0.0f; row[2] = 0.0f; row[3] = 0.0f;
            row[4] = 0.0f; row[5] = -1.0f;
        }
        if (write_keep)
            out[(size_t)Bn * MAXN * 6 + b * MAXN + tid] = kept ? 1.0f : 0.0f;
    }

    // re-zero per-batch counter for the next graph replay
    if (tid == 0) g_cnt[b] = 0;
}

// ---------------- host launcher ----------------
extern "C" void kernel_launch(void* const* d_in, const int* in_sizes, int n_in,
                              void* d_out, int out_size) {
    const float* cls    = nullptr;
    const float* bbox   = nullptr;
    const float* obj    = nullptr;
    const float* priors = nullptr;
    for (int i = 0; i < n_in; i++) {
        int sz = in_sizes[i];
        if      (sz == Bn * Nn * Cc) cls    = (const float*)d_in[i];
        else if (sz == Bn * Nn * 4)  bbox   = (const float*)d_in[i];
        else if (sz == Bn * Nn)      obj    = (const float*)d_in[i];
        else if (sz == Nn * 4)       priors = (const float*)d_in[i];
    }
    float* out = (float*)d_out;
    int write_keep = (out_size >= Bn * MAXN * 6 + Bn * MAXN) ? 1 : 0;

    int total_threads = Bn * Nn * 4;
    k_score<<<(total_threads + 255) / 256, 256>>>(cls, obj);
    k_compact<<<Bn * SLICES, 256>>>(bbox, priors);
    k_nms<<<Bn, 1024>>>(out, write_keep);
}

// round 12
// speedup vs baseline: 1.0458x; 1.0458x over previous
#include <cuda_runtime.h>
#include <cuda_bf16.h>
#include <float.h>
#include <math.h>
#include <stdint.h>

// ---------------- problem constants ----------------
constexpr int   Bn   = 16;
constexpr int   Nn   = 33600;
constexpr int   Cc   = 80;
constexpr int   MAXN = 100;
constexpr float THR  = 0.05f;
constexpr float IOUT = 0.65f;

// histogram constants: bucket = (bits - BASE) >> 14
constexpr unsigned BASE = 0x3D000000u;   // below bits(0.05)=0x3D4CCCCD
constexpr int      HB    = 2560;         // (0x3F800000-BASE)>>14
constexpr int      HBPAD = 3072;         // 1024*3 for the scan
constexpr int      CAP   = 1024;         // candidate capacity per batch

constexpr int   TPB        = 1024;
constexpr int   ANCH_CTA   = TPB / 4;            // 256 anchors per score CTA
constexpr int   SCORE_CTAS = Bn * Nn / ANCH_CTA; // 2100
constexpr int   NV         = (Nn / 2 + TPB - 1) / TPB;  // 9 uint4 per select thread

// ---------------- device scratch ----------------
__device__ uint2 g_sl[Bn * Nn];   // {score_bits (0 if <THR), label}
__device__ int   g_done[Bn];      // anchors scored per batch; reset by select CTA

// intra-warp inclusive suffix sum over 32 lanes
__device__ __forceinline__ unsigned warp_suffix_sum(unsigned v, int lane) {
#pragma unroll
    for (int o = 1; o < 32; o <<= 1) {
        unsigned u = __shfl_down_sync(0xffffffffu, v, o);
        if (lane + o < 32) v += u;
    }
    return v;
}

__global__ void __launch_bounds__(TPB, 1)
k_all(const float* __restrict__ cls,
      const float* __restrict__ obj,
      const float* __restrict__ bbox,
      const float* __restrict__ priors,
      float* __restrict__ out,
      int write_keep) {
    // select-role shared state (allocated for all CTAs; score role ignores it)
    __shared__ unsigned           hist[HBPAD];
    __shared__ unsigned           csum[1024];
    __shared__ unsigned           wsum[32];
    __shared__ unsigned long long cand[CAP];
    __shared__ int                spos[128];
    __shared__ int                misc[2];
    __shared__ float4             bx4[MAXN];
    __shared__ float              ars[MAXN];
    __shared__ float              sss[MAXN];
    __shared__ int                lls[MAXN];
    __shared__ unsigned           sup[MAXN][4];
    __shared__ unsigned           kin[4];
    __shared__ unsigned           kout[4];

    int bid = blockIdx.x;
    int tid = threadIdx.x;

    if (bid < SCORE_CTAS) {
        // ================= score role =================
        int t   = bid * TPB + tid;
        int a   = t >> 2;
        int sub = t & 3;

        const float4* p = reinterpret_cast<const float4*>(cls + (size_t)a * Cc + sub * 20);
        float mx = -FLT_MAX;
        int   mi = 0;
#pragma unroll
        for (int i = 0; i < 5; i++) {
            float4 v = p[i];
            int base = sub * 20 + i * 4;
            if (v.x > mx) { mx = v.x; mi = base; }
            if (v.y > mx) { mx = v.y; mi = base + 1; }
            if (v.z > mx) { mx = v.z; mi = base + 2; }
            if (v.w > mx) { mx = v.w; mi = base + 3; }
        }
#pragma unroll
        for (int off = 1; off < 4; off <<= 1) {
            float om  = __shfl_xor_sync(0xffffffffu, mx, off);
            int   omi = __shfl_xor_sync(0xffffffffu, mi, off);
            if (om > mx || (om == mx && omi < mi)) { mx = om; mi = omi; }
        }
        if (sub == 0) {
            float o = obj[a];
            float s = (1.0f / (1.0f + __expf(-mx))) * (1.0f / (1.0f + __expf(-o)));
            unsigned bits = (s >= THR) ? __float_as_uint(s) : 0u;
            g_sl[a] = make_uint2(bits, (unsigned)mi);
        }
        __syncthreads();
        if (tid == 0) {
            __threadfence();                       // release this CTA's g_sl writes
            int lo = bid * ANCH_CTA, hi = lo + ANCH_CTA;
            int b0 = lo / Nn, b1 = (hi - 1) / Nn;
            if (b0 == b1) {
                atomicAdd(&g_done[b0], ANCH_CTA);
            } else {
                int mid = (b0 + 1) * Nn;
                atomicAdd(&g_done[b0], mid - lo);
                atomicAdd(&g_done[b1], hi - mid);
            }
        }
        return;
    }

    // ================= select + NMS role =================
    int b    = bid - SCORE_CTAS;
    int lane = tid & 31;
    int wid  = tid >> 5;

    // wait for all of this batch's scores
    if (tid == 0) {
        volatile int* dp = g_done + b;
        while (*dp < Nn) __nanosleep(256);
    }
    __syncthreads();
    __threadfence();   // acquire

    // preload this batch's packed scores into registers (one pass over 67KB)
    const uint4* sp = reinterpret_cast<const uint4*>(g_sl + (size_t)b * Nn);
    uint4 v[NV];
#pragma unroll
    for (int k = 0; k < NV; k++) {
        int i = tid + k * TPB;
        v[k] = (i < Nn / 2) ? sp[i] : make_uint4(0u, 0u, 0u, 0u);
    }

    // smem histogram
#pragma unroll
    for (int k = 0; k < HBPAD / TPB; k++) hist[tid + k * TPB] = 0u;
    if (tid == 0) { misc[0] = 0; misc[1] = 0; }
    if (tid < 4)  kin[tid] = 0u;
    __syncthreads();
#pragma unroll
    for (int k = 0; k < NV; k++) {
        if (v[k].x) {
            unsigned bk = (v[k].x - BASE) >> 14;
            if (bk >= (unsigned)HB) bk = HB - 1;
            atomicAdd(&hist[bk], 1u);
        }
        if (v[k].z) {
            unsigned bk = (v[k].z - BASE) >> 14;
            if (bk >= (unsigned)HB) bk = HB - 1;
            atomicAdd(&hist[bk], 1u);
        }
    }
    __syncthreads();

    // suffix scan over 1024 chunk sums (3 buckets/thread)
    unsigned cs = hist[tid * 3] + hist[tid * 3 + 1] + hist[tid * 3 + 2];
    unsigned suf = warp_suffix_sum(cs, lane);
    if (lane == 0) wsum[wid] = suf;
    __syncthreads();
    if (wid == 0) {
        unsigned wv = wsum[lane];
        wsum[lane] = warp_suffix_sum(wv, lane);
    }
    __syncthreads();
    unsigned suffTotal = suf + ((wid < 31) ? wsum[wid + 1] : 0u);
    csum[tid] = suffTotal;
    __syncthreads();
    if (suffTotal >= (unsigned)MAXN &&
        (tid == 1023 || csum[tid + 1] < (unsigned)MAXN))
        misc[0] = tid;
    __syncthreads();
    if (tid == 0) {
        int c = misc[0];
        int cum = (c < 1023) ? (int)csum[c + 1] : 0;
        int bstart = c * 3;
        int bb = bstart + 2;
        for (; bb >= bstart; bb--) {
            cum += (int)hist[bb];
            if (cum >= MAXN) break;
        }
        int bucket = (bb < bstart) ? bstart : bb;
        misc[0] = (int)(BASE + ((unsigned)bucket << 14));
    }
    __syncthreads();
    unsigned TB = (unsigned)misc[0];

    // compact from registers
#pragma unroll
    for (int k = 0; k < NV; k++) {
        int i = tid + k * TPB;
#pragma unroll
        for (int h = 0; h < 2; h++) {
            unsigned bits = h ? v[k].z : v[k].x;
            if (bits >= TB && i < Nn / 2) {
                int idx = 2 * i + h;
                int pos = atomicAdd(&misc[1], 1);
                if (pos < CAP)
                    cand[pos] = ((unsigned long long)bits << 32) | (unsigned)(~idx);
            }
        }
    }
    __syncthreads();
    int cnt = misc[1]; if (cnt > CAP) cnt = CAP;

    // exact rank (keys unique)
    if (tid < 128) spos[tid] = -1;
    __syncthreads();
    if (tid < cnt) {
        unsigned long long mk = cand[tid];
        int r = 0;
        for (int j = 0; j < cnt; j++) r += (cand[j] > mk);
        if (r < 128) spos[r] = tid;
    }
    __syncthreads();

    // decode winners
    if (tid < MAXN) {
        sup[tid][0] = 0u; sup[tid][1] = 0u; sup[tid][2] = 0u; sup[tid][3] = 0u;
        int p = spos[tid];
        if (p >= 0) {
            unsigned long long key = cand[p];
            int idx = (int)(~(unsigned)(key & 0xffffffffu));
            float4 pr = reinterpret_cast<const float4*>(priors)[idx];
            float4 bp = reinterpret_cast<const float4*>(bbox)[(size_t)b * Nn + idx];
            float cx = bp.x * pr.z + pr.x;
            float cy = bp.y * pr.w + pr.y;
            float w  = __expf(bp.z) * pr.z;
            float h  = __expf(bp.w) * pr.w;
            bx4[tid] = make_float4(cx - 0.5f * w, cy - 0.5f * h,
                                   cx + 0.5f * w, cy + 0.5f * h);
            ars[tid] = w * h;
            sss[tid] = __uint_as_float((unsigned)(key >> 32));
            lls[tid] = (int)g_sl[(size_t)b * Nn + idx].y;
            atomicOr(&kin[tid >> 5], 1u << (tid & 31));
        } else {
            bx4[tid] = make_float4(0.f, 0.f, 0.f, 0.f);
            ars[tid] = 0.f; sss[tid] = 0.f; lls[tid] = -1;
        }
    }
    __syncthreads();

    // parallel pairwise suppression matrix
    for (int p = tid; p < MAXN * MAXN; p += TPB) {
        int i = p / MAXN;
        int r = p - i * MAXN;
        if (r > i) {
            int li = lls[i];
            if (li >= 0 && li == lls[r]) {
                float4 bi = bx4[i];
                float4 br = bx4[r];
                float ix1 = fmaxf(br.x, bi.x);
                float iy1 = fmaxf(br.y, bi.y);
                float ix2 = fminf(br.z, bi.z);
                float iy2 = fminf(br.w, bi.w);
                float inter = fmaxf(ix2 - ix1, 0.0f) * fmaxf(iy2 - iy1, 0.0f);
                float uni   = ars[i] + ars[r] - inter;
                if (inter / (uni + 1e-8f) >= IOUT)
                    atomicOr(&sup[i][r >> 5], 1u << (r & 31));
            }
        }
    }
    __syncthreads();

    // greedy scan: software-pipelined register bit logic
    if (tid == 0) {
        unsigned k0 = kin[0], k1 = kin[1], k2 = kin[2], k3 = kin[3];
        unsigned n0 = sup[0][0], n1 = sup[0][1], n2 = sup[0][2], n3 = sup[0][3];
        for (int i = 0; i < MAXN - 1; i++) {
            unsigned c0 = n0, c1 = n1, c2 = n2, c3 = n3;
            n0 = sup[i + 1][0]; n1 = sup[i + 1][1];
            n2 = sup[i + 1][2]; n3 = sup[i + 1][3];
            unsigned kw = (i < 32) ? k0 : (i < 64) ? k1 : (i < 96) ? k2 : k3;
            if ((kw >> (i & 31)) & 1u) {
                k0 &= ~c0; k1 &= ~c1; k2 &= ~c2; k3 &= ~c3;
            }
        }
        kout[0] = k0; kout[1] = k1; kout[2] = k2; kout[3] = k3;
    }
    __syncthreads();

    // write output
    if (tid < MAXN) {
        bool kept = (kout[tid >> 5] >> (tid & 31)) & 1u;
        float* row = out + ((size_t)b * MAXN + tid) * 6;
        if (kept) {
            float4 bb = bx4[tid];
            row[0] = bb.x; row[1] = bb.y; row[2] = bb.z; row[3] = bb.w;
            row[4] = sss[tid]; row[5] = (float)lls[tid];
        } else {
            row[0] = 0.0f; row[1] = 0.0f; row[2] = 0.0f; row[3] = 0.0f;
            row[4] = 0.0f; row[5] = -1.0f;
        }
        if (write_keep)
            out[(size_t)Bn * MAXN * 6 + b * MAXN + tid] = kept ? 1.0f : 0.0f;
    }

    // reset the per-batch done counter for the next graph replay
    if (tid == 0) g_done[b] = 0;
}

// ---------------- host launcher ----------------
extern "C" void kernel_launch(void* const* d_in, const int* in_sizes, int n_in,
                              void* d_out, int out_size) {
    const float* cls    = nullptr;
    const float* bbox   = nullptr;
    const float* obj    = nullptr;
    const float* priors = nullptr;
    for (int i = 0; i < n_in; i++) {
        int sz = in_sizes[i];
        if      (sz == Bn * Nn * Cc) cls    = (const float*)d_in[i];
        else if (sz == Bn * Nn * 4)  bbox   = (const float*)d_in[i];
        else if (sz == Bn * Nn)      obj    = (const float*)d_in[i];
        else if (sz == Nn * 4)       priors = (const float*)d_in[i];
    }
    float* out = (float*)d_out;
    int write_keep = (out_size >= Bn * MAXN * 6 + Bn * MAXN) ? 1 : 0;

    k_all<<<SCORE_CTAS + Bn, TPB>>>(cls, obj, bbox, priors, out, write_keep);
}

// round 13
// speedup vs baseline: 1.4102x; 1.3484x over previous
#include <cuda_runtime.h>
#include <cuda_bf16.h>
#include <float.h>
#include <math.h>
#include <stdint.h>

// ---------------- problem constants ----------------
constexpr int   Bn   = 16;
constexpr int   Nn   = 33600;
constexpr int   Cc   = 80;
constexpr int   MAXN = 100;
constexpr float THR  = 0.05f;
constexpr float IOUT = 0.65f;

// histogram constants: bucket = (bits - BASE) >> 14
constexpr unsigned BASE = 0x3D000000u;   // below bits(0.05)=0x3D4CCCCD
constexpr int      HB    = 2560;         // (0x3F800000-BASE)>>14
constexpr int      HBPAD = 3072;         // 1024*3 for the scan
constexpr int      CAP   = 1024;         // candidate capacity per batch

constexpr int   TPB        = 1024;
constexpr int   ANCH_CTA   = TPB / 4;            // 256 anchors per score CTA
constexpr int   SCORE_CTAS = Bn * Nn / ANCH_CTA; // 2100
constexpr int   SEL_CTAS   = Bn;                 // select CTAs at bids 0..15

// ---------------- device scratch ----------------
__device__ uint2 g_sl[Bn * Nn];   // {score_bits (0 if <THR), label}
__device__ int   g_done[Bn];      // anchors scored per batch; reset by select CTA

// intra-warp inclusive suffix sum over 32 lanes
__device__ __forceinline__ unsigned warp_suffix_sum(unsigned v, int lane) {
#pragma unroll
    for (int o = 1; o < 32; o <<= 1) {
        unsigned u = __shfl_down_sync(0xffffffffu, v, o);
        if (lane + o < 32) v += u;
    }
    return v;
}

__global__ void __launch_bounds__(TPB, 2)
k_all(const float* __restrict__ cls,
      const float* __restrict__ obj,
      const float* __restrict__ bbox,
      const float* __restrict__ priors,
      float* __restrict__ out,
      int write_keep) {
    __shared__ unsigned           hist[HBPAD];
    __shared__ unsigned           csum[1024];
    __shared__ unsigned           wsum[32];
    __shared__ unsigned long long cand[CAP];
    __shared__ int                spos[128];
    __shared__ int                misc[2];
    __shared__ float4             bx4[MAXN];
    __shared__ float              ars[MAXN];
    __shared__ float              sss[MAXN];
    __shared__ int                lls[MAXN];
    __shared__ unsigned           sup[MAXN][4];
    __shared__ unsigned           kin[4];
    __shared__ unsigned           kout[4];

    int bid = blockIdx.x;
    int tid = threadIdx.x;

    if (bid >= SEL_CTAS) {
        // ================= score role (bids 16..2115) =================
        int t   = (bid - SEL_CTAS) * TPB + tid;
        int a   = t >> 2;
        int sub = t & 3;

        const float4* p = reinterpret_cast<const float4*>(cls + (size_t)a * Cc + sub * 20);
        float mx = -FLT_MAX;
        int   mi = 0;
#pragma unroll
        for (int i = 0; i < 5; i++) {
            float4 v = p[i];
            int base = sub * 20 + i * 4;
            if (v.x > mx) { mx = v.x; mi = base; }
            if (v.y > mx) { mx = v.y; mi = base + 1; }
            if (v.z > mx) { mx = v.z; mi = base + 2; }
            if (v.w > mx) { mx = v.w; mi = base + 3; }
        }
#pragma unroll
        for (int off = 1; off < 4; off <<= 1) {
            float om  = __shfl_xor_sync(0xffffffffu, mx, off);
            int   omi = __shfl_xor_sync(0xffffffffu, mi, off);
            if (om > mx || (om == mx && omi < mi)) { mx = om; mi = omi; }
        }
        if (sub == 0) {
            float o = obj[a];
            float s = (1.0f / (1.0f + __expf(-mx))) * (1.0f / (1.0f + __expf(-o)));
            unsigned bits = (s >= THR) ? __float_as_uint(s) : 0u;
            g_sl[a] = make_uint2(bits, (unsigned)mi);
        }
        __syncthreads();
        if (tid == 0) {
            __threadfence();                       // release this CTA's g_sl writes
            int lo = (bid - SEL_CTAS) * ANCH_CTA, hi = lo + ANCH_CTA;
            int b0 = lo / Nn, b1 = (hi - 1) / Nn;
            if (b0 == b1) {
                atomicAdd(&g_done[b0], ANCH_CTA);
            } else {
                int mid = (b0 + 1) * Nn;
                atomicAdd(&g_done[b0], mid - lo);
                atomicAdd(&g_done[b1], hi - mid);
            }
        }
        return;
    }

    // ================= select + NMS role (bids 0..15) =================
    int b    = bid;
    int lane = tid & 31;
    int wid  = tid >> 5;

    // init smem while waiting
#pragma unroll
    for (int k = 0; k < HBPAD / TPB; k++) hist[tid + k * TPB] = 0u;
    if (tid == 0) { misc[0] = 0; misc[1] = 0; }
    if (tid < 4)  kin[tid] = 0u;
    if (tid < 128) spos[tid] = -1;

    // wait for all of this batch's scores
    if (tid == 0) {
        volatile int* dp = g_done + b;
        while (*dp < Nn) __nanosleep(128);
    }
    __syncthreads();
    __threadfence();   // acquire

    const uint4* sp = reinterpret_cast<const uint4*>(g_sl + (size_t)b * Nn);

    // pass 1: smem histogram
#pragma unroll 2
    for (int i = tid; i < Nn / 2; i += TPB) {
        uint4 v = sp[i];
        if (v.x) {
            unsigned bk = (v.x - BASE) >> 14;
            if (bk >= (unsigned)HB) bk = HB - 1;
            atomicAdd(&hist[bk], 1u);
        }
        if (v.z) {
            unsigned bk = (v.z - BASE) >> 14;
            if (bk >= (unsigned)HB) bk = HB - 1;
            atomicAdd(&hist[bk], 1u);
        }
    }
    __syncthreads();

    // suffix scan over 1024 chunk sums (3 buckets/thread)
    unsigned cs = hist[tid * 3] + hist[tid * 3 + 1] + hist[tid * 3 + 2];
    unsigned suf = warp_suffix_sum(cs, lane);
    if (lane == 0) wsum[wid] = suf;
    __syncthreads();
    if (wid == 0) {
        unsigned wv = wsum[lane];
        wsum[lane] = warp_suffix_sum(wv, lane);
    }
    __syncthreads();
    unsigned suffTotal = suf + ((wid < 31) ? wsum[wid + 1] : 0u);
    csum[tid] = suffTotal;
    __syncthreads();
    if (suffTotal >= (unsigned)MAXN &&
        (tid == 1023 || csum[tid + 1] < (unsigned)MAXN))
        misc[0] = tid;
    __syncthreads();
    if (tid == 0) {
        int c = misc[0];
        int cum = (c < 1023) ? (int)csum[c + 1] : 0;
        int bstart = c * 3;
        int bb = bstart + 2;
        for (; bb >= bstart; bb--) {
            cum += (int)hist[bb];
            if (cum >= MAXN) break;
        }
        int bucket = (bb < bstart) ? bstart : bb;
        misc[0] = (int)(BASE + ((unsigned)bucket << 14));
    }
    __syncthreads();
    unsigned TB = (unsigned)misc[0];

    // pass 2: compact (L2-resident re-read)
#pragma unroll 2
    for (int i = tid; i < Nn / 2; i += TPB) {
        uint4 v = sp[i];
        if (v.x >= TB) {
            int pos = atomicAdd(&misc[1], 1);
            if (pos < CAP)
                cand[pos] = ((unsigned long long)v.x << 32) | (unsigned)(~(2 * i));
        }
        if (v.z >= TB) {
            int pos = atomicAdd(&misc[1], 1);
            if (pos < CAP)
                cand[pos] = ((unsigned long long)v.z << 32) | (unsigned)(~(2 * i + 1));
        }
    }
    __syncthreads();
    int cnt = misc[1]; if (cnt > CAP) cnt = CAP;

    // exact rank (keys unique)
    if (tid < cnt) {
        unsigned long long mk = cand[tid];
        int r = 0;
        for (int j = 0; j < cnt; j++) r += (cand[j] > mk);
        if (r < 128) spos[r] = tid;
    }
    __syncthreads();

    // decode winners
    if (tid < MAXN) {
        sup[tid][0] = 0u; sup[tid][1] = 0u; sup[tid][2] = 0u; sup[tid][3] = 0u;
        int p = spos[tid];
        if (p >= 0) {
            unsigned long long key = cand[p];
            int idx = (int)(~(unsigned)(key & 0xffffffffu));
            float4 pr = reinterpret_cast<const float4*>(priors)[idx];
            float4 bp = reinterpret_cast<const float4*>(bbox)[(size_t)b * Nn + idx];
            float cx = bp.x * pr.z + pr.x;
            float cy = bp.y * pr.w + pr.y;
            float w  = __expf(bp.z) * pr.z;
            float h  = __expf(bp.w) * pr.w;
            bx4[tid] = make_float4(cx - 0.5f * w, cy - 0.5f * h,
                                   cx + 0.5f * w, cy + 0.5f * h);
            ars[tid] = w * h;
            sss[tid] = __uint_as_float((unsigned)(key >> 32));
            lls[tid] = (int)g_sl[(size_t)b * Nn + idx].y;
            atomicOr(&kin[tid >> 5], 1u << (tid & 31));
        } else {
            bx4[tid] = make_float4(0.f, 0.f, 0.f, 0.f);
            ars[tid] = 0.f; sss[tid] = 0.f; lls[tid] = -1;
        }
    }
    __syncthreads();

    // parallel pairwise suppression matrix
    for (int p = tid; p < MAXN * MAXN; p += TPB) {
        int i = p / MAXN;
        int r = p - i * MAXN;
        if (r > i) {
            int li = lls[i];
            if (li >= 0 && li == lls[r]) {
                float4 bi = bx4[i];
                float4 br = bx4[r];
                float ix1 = fmaxf(br.x, bi.x);
                float iy1 = fmaxf(br.y, bi.y);
                float ix2 = fminf(br.z, bi.z);
                float iy2 = fminf(br.w, bi.w);
                float inter = fmaxf(ix2 - ix1, 0.0f) * fmaxf(iy2 - iy1, 0.0f);
                float uni   = ars[i] + ars[r] - inter;
                if (inter / (uni + 1e-8f) >= IOUT)
                    atomicOr(&sup[i][r >> 5], 1u << (r & 31));
            }
        }
    }
    __syncthreads();

    // greedy scan: software-pipelined register bit logic
    if (tid == 0) {
        unsigned k0 = kin[0], k1 = kin[1], k2 = kin[2], k3 = kin[3];
        unsigned n0 = sup[0][0], n1 = sup[0][1], n2 = sup[0][2], n3 = sup[0][3];
        for (int i = 0; i < MAXN - 1; i++) {
            unsigned c0 = n0, c1 = n1, c2 = n2, c3 = n3;
            n0 = sup[i + 1][0]; n1 = sup[i + 1][1];
            n2 = sup[i + 1][2]; n3 = sup[i + 1][3];
            unsigned kw = (i < 32) ? k0 : (i < 64) ? k1 : (i < 96) ? k2 : k3;
            if ((kw >> (i & 31)) & 1u) {
                k0 &= ~c0; k1 &= ~c1; k2 &= ~c2; k3 &= ~c3;
            }
        }
        kout[0] = k0; kout[1] = k1; kout[2] = k2; kout[3] = k3;
    }
    __syncthreads();

    // write output
    if (tid < MAXN) {
        bool kept = (kout[tid >> 5] >> (tid & 31)) & 1u;
        float* row = out + ((size_t)b * MAXN + tid) * 6;
        if (kept) {
            float4 bb = bx4[tid];
            row[0] = bb.x; row[1] = bb.y; row[2] = bb.z; row[3] = bb.w;
            row[4] = sss[tid]; row[5] = (float)lls[tid];
        } else {
            row[0] = 0.0f; row[1] = 0.0f; row[2] = 0.0f; row[3] = 0.0f;
            row[4] = 0.0f; row[5] = -1.0f;
        }
        if (write_keep)
            out[(size_t)Bn * MAXN * 6 + b * MAXN + tid] = kept ? 1.0f : 0.0f;
    }

    // reset the per-batch done counter for the next graph replay
    if (tid == 0) g_done[b] = 0;
}

// ---------------- host launcher ----------------
extern "C" void kernel_launch(void* const* d_in, const int* in_sizes, int n_in,
                              void* d_out, int out_size) {
    const float* cls    = nullptr;
    const float* bbox   = nullptr;
    const float* obj    = nullptr;
    const float* priors = nullptr;
    for (int i = 0; i < n_in; i++) {
        int sz = in_sizes[i];
        if      (sz == Bn * Nn * Cc) cls    = (const float*)d_in[i];
        else if (sz == Bn * Nn * 4)  bbox   = (const float*)d_in[i];
        else if (sz == Bn * Nn)      obj    = (const float*)d_in[i];
        else if (sz == Nn * 4)       priors = (const float*)d_in[i];
    }
    float* out = (float*)d_out;
    int write_keep = (out_size >= Bn * MAXN * 6 + Bn * MAXN) ? 1 : 0;

    k_all<<<SEL_CTAS + SCORE_CTAS, TPB>>>(cls, obj, bbox, priors, out, write_keep);
}